// round 9
// baseline (speedup 1.0000x reference)
#include <cuda_runtime.h>
#include <stdint.h>

#define NODES 50000
#define EDGES 800000
#define DD    128
#define EPS   1e-5f
#define NCHUNK 4

// ---------------- scratch (static device globals; no allocation) ----------------
__device__ float g_agg[(size_t)NODES * DD];
__device__ float g_h1[(size_t)NODES * DD];   // raw pre-BN layer-0 output
__device__ float g_h2[(size_t)NODES * DD];   // raw pre-BN layer-1 output
__device__ float g_rdeg[NODES];
__device__ int   g_deg[NODES];
__device__ int   g_csr_ptr[NODES + 1];
__device__ int   g_cursor[NODES];
__device__ int   g_csr_src[EDGES];
__device__ int   g_bsum[256];
__device__ int   g_boff[256];
__device__ float g_stats[2 * DD];            // col sums / sumsq (reset by finalize)
__device__ float g_sc[DD];                   // lazy-BN scale per column
__device__ float g_sh[DD];                   // lazy-BN shift per column

// ---------------- degree + CSR build ----------------
__global__ void k_count_deg(const int* __restrict__ dst, int e) {
    int i = blockIdx.x * blockDim.x + threadIdx.x;
    if (i < e) atomicAdd(&g_deg[dst[i]], 1);
}

__global__ void k_scan1(int n) {
    __shared__ int s[256];
    int tid = threadIdx.x;
    int i = blockIdx.x * 256 + tid;
    int v = (i < n) ? g_deg[i] : 0;
    s[tid] = v;
    __syncthreads();
#pragma unroll
    for (int o = 1; o < 256; o <<= 1) {
        int x = (tid >= o) ? s[tid - o] : 0;
        __syncthreads();
        s[tid] += x;
        __syncthreads();
    }
    if (i < n) g_csr_ptr[i] = s[tid] - v;
    if (tid == 255) g_bsum[blockIdx.x] = s[255];
}

__global__ void k_scan2(int nb) {
    __shared__ int s[256];
    int tid = threadIdx.x;
    int v = (tid < nb) ? g_bsum[tid] : 0;
    s[tid] = v;
    __syncthreads();
#pragma unroll
    for (int o = 1; o < 256; o <<= 1) {
        int x = (tid >= o) ? s[tid - o] : 0;
        __syncthreads();
        s[tid] += x;
        __syncthreads();
    }
    if (tid < nb) g_boff[tid] = s[tid] - v;
}

__global__ void k_scan3(int n, int e) {
    int i = blockIdx.x * blockDim.x + threadIdx.x;
    if (i < n) {
        int p = g_csr_ptr[i] + g_boff[blockIdx.x];
        g_csr_ptr[i] = p;
        g_cursor[i] = p;
        int d = g_deg[i];
        g_rdeg[i] = 1.0f / (float)(d > 0 ? d : 1);
    }
    if (i == 0) g_csr_ptr[n] = e;
}

__global__ void k_fill(const int* __restrict__ src, const int* __restrict__ dst, int e) {
    int i = blockIdx.x * blockDim.x + threadIdx.x;
    if (i < e) {
        int pos = atomicAdd(&g_cursor[dst[i]], 1);
        g_csr_src[pos] = src[i];
    }
}

// ---------------- gather: one warp per dst node; lazy BN+ReLU on input ----------------
template<bool BN>
__global__ __launch_bounds__(256)
void k_gather(const float* __restrict__ h, int n0, int n1) {
    int node = n0 + ((blockIdx.x * blockDim.x + threadIdx.x) >> 5);
    int lane = threadIdx.x & 31;
    if (node >= n1) return;
    float4 sc, sh;
    if (BN) {
        sc = *reinterpret_cast<const float4*>(g_sc + lane * 4);
        sh = *reinterpret_cast<const float4*>(g_sh + lane * 4);
    }
    int beg = g_csr_ptr[node];
    int end = g_csr_ptr[node + 1];
    float4 acc = make_float4(0.f, 0.f, 0.f, 0.f);
    for (int base = beg; base < end; base += 32) {
        int mye = base + lane;
        int sidx = (mye < end) ? g_csr_src[mye] : 0;
        int cnt = min(32, end - base);
        int i = 0;
        for (; i + 1 < cnt; i += 2) {
            int s0 = __shfl_sync(0xffffffffu, sidx, i);
            int s1 = __shfl_sync(0xffffffffu, sidx, i + 1);
            float4 v0 = *reinterpret_cast<const float4*>(h + (size_t)s0 * DD + lane * 4);
            float4 v1 = *reinterpret_cast<const float4*>(h + (size_t)s1 * DD + lane * 4);
            if (BN) {
                v0.x = fmaxf(fmaf(v0.x, sc.x, sh.x), 0.f);
                v0.y = fmaxf(fmaf(v0.y, sc.y, sh.y), 0.f);
                v0.z = fmaxf(fmaf(v0.z, sc.z, sh.z), 0.f);
                v0.w = fmaxf(fmaf(v0.w, sc.w, sh.w), 0.f);
                v1.x = fmaxf(fmaf(v1.x, sc.x, sh.x), 0.f);
                v1.y = fmaxf(fmaf(v1.y, sc.y, sh.y), 0.f);
                v1.z = fmaxf(fmaf(v1.z, sc.z, sh.z), 0.f);
                v1.w = fmaxf(fmaf(v1.w, sc.w, sh.w), 0.f);
            }
            acc.x += v0.x; acc.y += v0.y; acc.z += v0.z; acc.w += v0.w;
            acc.x += v1.x; acc.y += v1.y; acc.z += v1.z; acc.w += v1.w;
        }
        if (i < cnt) {
            int s0 = __shfl_sync(0xffffffffu, sidx, i);
            float4 v0 = *reinterpret_cast<const float4*>(h + (size_t)s0 * DD + lane * 4);
            if (BN) {
                v0.x = fmaxf(fmaf(v0.x, sc.x, sh.x), 0.f);
                v0.y = fmaxf(fmaf(v0.y, sc.y, sh.y), 0.f);
                v0.z = fmaxf(fmaf(v0.z, sc.z, sh.z), 0.f);
                v0.w = fmaxf(fmaf(v0.w, sc.w, sh.w), 0.f);
            }
            acc.x += v0.x; acc.y += v0.y; acc.z += v0.z; acc.w += v0.w;
        }
    }
    float rd = g_rdeg[node];
    acc.x *= rd; acc.y *= rd; acc.z *= rd; acc.w *= rd;
    *reinterpret_cast<float4*>(g_agg + (size_t)node * DD + lane * 4) = acc;
}

// ---------------- tf32 tensor-core dual GEMM + bias + residual (lazy BN input) ------
__device__ __forceinline__ uint32_t f2tf32(float x) {
    uint32_t r;
    asm("cvt.rna.tf32.f32 %0, %1;" : "=r"(r) : "f"(x));
    return r;
}

__device__ __forceinline__ void mma_tf32(float* d, const uint32_t* a, const uint32_t* b) {
    asm volatile(
        "mma.sync.aligned.m16n8k8.row.col.f32.tf32.tf32.f32 "
        "{%0,%1,%2,%3}, {%4,%5,%6,%7}, {%8,%9}, {%0,%1,%2,%3};\n"
        : "+f"(d[0]), "+f"(d[1]), "+f"(d[2]), "+f"(d[3])
        : "r"(a[0]), "r"(a[1]), "r"(a[2]), "r"(a[3]), "r"(b[0]), "r"(b[1]));
}

#define BM 128
#define BK 16
#define A_STRIDE 20
#define B_STRIDE 136

// BNIN: input h is raw pre-BN; apply x*sc+sh then relu at every read of h.
template<bool BNIN>
__global__ __launch_bounds__(256, 2)
void k_gemm_tc(const float* __restrict__ h,
               const float* __restrict__ Ws, const float* __restrict__ Wn,
               const float* __restrict__ bias, float* __restrict__ out,
               int nrows, int mbase) {
    __shared__ uint32_t Ah[128][A_STRIDE];
    __shared__ uint32_t Aa[128][A_STRIDE];
    __shared__ uint32_t Bs[BK][B_STRIDE];
    __shared__ uint32_t Bn[BK][B_STRIDE];

    const int tid  = threadIdx.x;
    const int warp = tid >> 5;
    const int lane = tid & 31;
    const int g    = lane >> 2;
    const int t    = lane & 3;
    const int wm   = warp & 3;
    const int wn   = warp >> 2;
    const int m0   = mbase + blockIdx.x * BM;
    const int wrow = wm * 32;
    const int wcol = wn * 64;

    float acc[2][8][4];
#pragma unroll
    for (int mt = 0; mt < 2; mt++)
#pragma unroll
        for (int nt = 0; nt < 8; nt++)
#pragma unroll
            for (int j = 0; j < 4; j++) acc[mt][nt][j] = 0.f;

    for (int kc = 0; kc < DD / BK; kc++) {
        const int ks = kc * BK;
#pragma unroll
        for (int r = 0; r < 2; r++) {
            int id  = tid + r * 256;
            int row = id >> 2;
            int c4  = id & 3;
            int grow = m0 + row;
            float4 vh = make_float4(0.f, 0.f, 0.f, 0.f);
            float4 va = make_float4(0.f, 0.f, 0.f, 0.f);
            if (grow < nrows) {
                size_t off = (size_t)grow * DD + ks + c4 * 4;
                vh = *reinterpret_cast<const float4*>(h + off);
                va = *reinterpret_cast<const float4*>(g_agg + off);
                if (BNIN) {
                    float4 s4 = *reinterpret_cast<const float4*>(g_sc + ks + c4 * 4);
                    float4 h4 = *reinterpret_cast<const float4*>(g_sh + ks + c4 * 4);
                    vh.x = fmaxf(fmaf(vh.x, s4.x, h4.x), 0.f);
                    vh.y = fmaxf(fmaf(vh.y, s4.y, h4.y), 0.f);
                    vh.z = fmaxf(fmaf(vh.z, s4.z, h4.z), 0.f);
                    vh.w = fmaxf(fmaf(vh.w, s4.w, h4.w), 0.f);
                }
            }
            uint4 ph = make_uint4(f2tf32(vh.x), f2tf32(vh.y), f2tf32(vh.z), f2tf32(vh.w));
            uint4 pa = make_uint4(f2tf32(va.x), f2tf32(va.y), f2tf32(va.z), f2tf32(va.w));
            *reinterpret_cast<uint4*>(&Ah[row][c4 * 4]) = ph;
            *reinterpret_cast<uint4*>(&Aa[row][c4 * 4]) = pa;
        }
#pragma unroll
        for (int r = 0; r < 2; r++) {
            int id  = tid + r * 256;
            int row = id >> 5;
            int c4  = id & 31;
            size_t off = (size_t)(ks + row) * DD + c4 * 4;
            float4 vs = *reinterpret_cast<const float4*>(Ws + off);
            float4 vn = *reinterpret_cast<const float4*>(Wn + off);
            uint4 ps = make_uint4(f2tf32(vs.x), f2tf32(vs.y), f2tf32(vs.z), f2tf32(vs.w));
            uint4 pn = make_uint4(f2tf32(vn.x), f2tf32(vn.y), f2tf32(vn.z), f2tf32(vn.w));
            *reinterpret_cast<uint4*>(&Bs[row][c4 * 4]) = ps;
            *reinterpret_cast<uint4*>(&Bn[row][c4 * 4]) = pn;
        }
        __syncthreads();

#pragma unroll
        for (int ks8 = 0; ks8 < BK / 8; ks8++) {
            const int kb = ks8 * 8;
            uint32_t a[2][4], b[8][2];
#pragma unroll
            for (int mt = 0; mt < 2; mt++) {
                int r = wrow + mt * 16;
                a[mt][0] = Ah[r + g][kb + t];
                a[mt][1] = Ah[r + g + 8][kb + t];
                a[mt][2] = Ah[r + g][kb + t + 4];
                a[mt][3] = Ah[r + g + 8][kb + t + 4];
            }
#pragma unroll
            for (int nt = 0; nt < 8; nt++) {
                int c = wcol + nt * 8 + g;
                b[nt][0] = Bs[kb + t][c];
                b[nt][1] = Bs[kb + t + 4][c];
            }
#pragma unroll
            for (int mt = 0; mt < 2; mt++)
#pragma unroll
                for (int nt = 0; nt < 8; nt++)
                    mma_tf32(acc[mt][nt], a[mt], b[nt]);
#pragma unroll
            for (int mt = 0; mt < 2; mt++) {
                int r = wrow + mt * 16;
                a[mt][0] = Aa[r + g][kb + t];
                a[mt][1] = Aa[r + g + 8][kb + t];
                a[mt][2] = Aa[r + g][kb + t + 4];
                a[mt][3] = Aa[r + g + 8][kb + t + 4];
            }
#pragma unroll
            for (int nt = 0; nt < 8; nt++) {
                int c = wcol + nt * 8 + g;
                b[nt][0] = Bn[kb + t][c];
                b[nt][1] = Bn[kb + t + 4][c];
            }
#pragma unroll
            for (int mt = 0; mt < 2; mt++)
#pragma unroll
                for (int nt = 0; nt < 8; nt++)
                    mma_tf32(acc[mt][nt], a[mt], b[nt]);
        }
        __syncthreads();
    }

    // epilogue: + bias + residual (residual = BN(h) when BNIN), write raw out
#pragma unroll
    for (int mt = 0; mt < 2; mt++) {
#pragma unroll
        for (int rr = 0; rr < 2; rr++) {
            int grow = m0 + wrow + mt * 16 + g + rr * 8;
            if (grow < nrows) {
#pragma unroll
                for (int nt = 0; nt < 8; nt++) {
                    int col = wcol + nt * 8 + t * 2;
                    size_t off = (size_t)grow * DD + col;
                    float2 res = *reinterpret_cast<const float2*>(h + off);
                    if (BNIN) {
                        float2 s2 = *reinterpret_cast<const float2*>(g_sc + col);
                        float2 h2 = *reinterpret_cast<const float2*>(g_sh + col);
                        res.x = fmaxf(fmaf(res.x, s2.x, h2.x), 0.f);
                        res.y = fmaxf(fmaf(res.y, s2.y, h2.y), 0.f);
                    }
                    float2 bv = *reinterpret_cast<const float2*>(bias + col);
                    float2 o;
                    o.x = acc[mt][nt][rr * 2 + 0] + bv.x + res.x;
                    o.y = acc[mt][nt][rr * 2 + 1] + bv.y + res.y;
                    *reinterpret_cast<float2*>(out + off) = o;
                }
            }
        }
    }
}

// ---------------- column stats (sum, sumsq) over raw pre-BN output ----------------
__global__ __launch_bounds__(256)
void k_stats(const float* __restrict__ x, int n) {
    __shared__ float sh[8][DD];
    __shared__ float shq[8][DD];
    int lane = threadIdx.x & 31;
    int w    = threadIdx.x >> 5;
    int c    = lane * 4;
    float4 s = make_float4(0.f, 0.f, 0.f, 0.f);
    float4 q = make_float4(0.f, 0.f, 0.f, 0.f);
    for (int r = blockIdx.x * 8 + w; r < n; r += gridDim.x * 8) {
        float4 v = *reinterpret_cast<const float4*>(x + (size_t)r * DD + c);
        s.x += v.x; s.y += v.y; s.z += v.z; s.w += v.w;
        q.x += v.x * v.x; q.y += v.y * v.y; q.z += v.z * v.z; q.w += v.w * v.w;
    }
    *reinterpret_cast<float4*>(&sh[w][c])  = s;
    *reinterpret_cast<float4*>(&shq[w][c]) = q;
    __syncthreads();
    if (threadIdx.x < DD) {
        float ss = 0.f, qq = 0.f;
#pragma unroll
        for (int r = 0; r < 8; r++) { ss += sh[r][threadIdx.x]; qq += shq[r][threadIdx.x]; }
        atomicAdd(&g_stats[threadIdx.x], ss);
        atomicAdd(&g_stats[DD + threadIdx.x], qq);
    }
}

// ---------------- finalize: stats -> (sc, sh), reset stats ----------------
__global__ void k_finalize(const float* __restrict__ gamma, const float* __restrict__ beta,
                           float n) {
    int i = threadIdx.x;
    if (i < DD) {
        float inv = 1.0f / n;
        float mu  = g_stats[i] * inv;
        float var = g_stats[DD + i] * inv - mu * mu;
        float scv = rsqrtf(var + EPS) * gamma[i];
        g_sc[i] = scv;
        g_sh[i] = beta[i] - mu * scv;
        g_stats[i] = 0.f;
        g_stats[DD + i] = 0.f;
    }
}

// ---------------- launch ----------------
extern "C" void kernel_launch(void* const* d_in, const int* in_sizes, int n_in,
                              void* d_out, int out_size) {
    const float* feat   = (const float*)d_in[0];
    const int*   src    = (const int*)d_in[1];
    const int*   dst    = (const int*)d_in[2];
    const float* Wself  = (const float*)d_in[3];
    const float* Wneigh = (const float*)d_in[4];
    const float* bias   = (const float*)d_in[5];
    const float* gamma  = (const float*)d_in[6];
    const float* beta   = (const float*)d_in[7];
    float* out = (float*)d_out;

    const int N = in_sizes[0] / DD;
    const int E = in_sizes[1];

    // streams / events: created once, outside capture (first call is uncaptured)
    static cudaStream_t s1 = nullptr;
    static cudaEvent_t evf;
    static cudaEvent_t evg[3 * NCHUNK];
    static cudaEvent_t evj[3];
    if (!s1) {
        cudaStreamCreateWithFlags(&s1, cudaStreamNonBlocking);
        cudaEventCreateWithFlags(&evf, cudaEventDisableTiming);
        for (int i = 0; i < 3 * NCHUNK; i++) cudaEventCreateWithFlags(&evg[i], cudaEventDisableTiming);
        for (int i = 0; i < 3; i++) cudaEventCreateWithFlags(&evj[i], cudaEventDisableTiming);
    }

    void *p_deg, *p_stats, *p_h1, *p_h2;
    cudaGetSymbolAddress(&p_deg, g_deg);
    cudaGetSymbolAddress(&p_stats, g_stats);
    cudaGetSymbolAddress(&p_h1, g_h1);
    cudaGetSymbolAddress(&p_h2, g_h2);

    // ---- CSR build (stream 0) ----
    const int nb = (N + 255) / 256;
    cudaMemsetAsync(p_deg, 0, (size_t)N * sizeof(int), 0);
    cudaMemsetAsync(p_stats, 0, 2 * DD * sizeof(float), 0);
    k_count_deg<<<(E + 255) / 256, 256, 0, 0>>>(dst, E);
    k_scan1<<<nb, 256, 0, 0>>>(N);
    k_scan2<<<1, 256, 0, 0>>>(nb);
    k_scan3<<<nb, 256, 0, 0>>>(N, E);
    k_fill<<<(E + 255) / 256, 256, 0, 0>>>(src, dst, E);

    // fork point for gemm stream
    cudaEventRecord(evf, 0);
    cudaStreamWaitEvent(s1, evf, 0);

    int cb[NCHUNK + 1];
    int step = ((N / NCHUNK) + BM - 1) / BM * BM;   // chunk size, multiple of BM
    for (int c = 0; c < NCHUNK; c++) cb[c] = c * step < N ? c * step : N;
    cb[NCHUNK] = N;

    const float* raw_in[3]  = {feat, (const float*)p_h1, (const float*)p_h2};
    float*       raw_out[3] = {(float*)p_h1, (float*)p_h2, out};

    for (int l = 0; l < 3; l++) {
        const float* Ws = Wself + (size_t)l * DD * DD;
        const float* Wn = Wneigh + (size_t)l * DD * DD;
        const float* bl = bias + (size_t)l * DD;
        const float* hin = raw_in[l];
        float* ho = raw_out[l];

        for (int c = 0; c < NCHUNK; c++) {
            int n0 = cb[c], n1 = cb[c + 1];
            if (n0 >= n1) continue;
            int gblocks = ((n1 - n0) + 7) / 8;
            if (l == 0) k_gather<false><<<gblocks, 256, 0, 0>>>(hin, n0, n1);
            else        k_gather<true ><<<gblocks, 256, 0, 0>>>(hin, n0, n1);
            cudaEventRecord(evg[l * NCHUNK + c], 0);
            cudaStreamWaitEvent(s1, evg[l * NCHUNK + c], 0);
            int mblocks = ((n1 - n0) + BM - 1) / BM;
            if (l == 0) k_gemm_tc<false><<<mblocks, 256, 0, s1>>>(hin, Ws, Wn, bl, ho, N, n0);
            else        k_gemm_tc<true ><<<mblocks, 256, 0, s1>>>(hin, Ws, Wn, bl, ho, N, n0);
        }

        if (l < 2) {
            k_stats<<<128, 256, 0, s1>>>((const float*)ho, N);
            k_finalize<<<1, 128, 0, s1>>>(gamma + (size_t)l * DD, beta + (size_t)l * DD, (float)N);
        }
        cudaEventRecord(evj[l], s1);
        cudaStreamWaitEvent(0, evj[l], 0);
    }
    (void)n_in; (void)out_size;
}